// round 16
// baseline (speedup 1.0000x reference)
#include <cuda_runtime.h>
#include <cuda_fp16.h>
#include <math.h>

#define NN 50000
#define EE 800000
#define HH 64
#define LL 14
#define INF_ 128
#define OUTF 112
#define MSG_EPS 1e-7f
#define LN_EPS 1e-5f
#define LOG2E 1.4426950408889634f
#define LN2   0.6931471805599453f

#define PGRID 912                 // 6 blocks/SM * 152 SMs
#define NP (NN / 2)               // node pairs: 25000

// packed f32x2 helpers (FFMA2 only reachable via PTX)
__device__ __forceinline__ unsigned long long pk2(float x, float y) {
    unsigned long long r;
    asm("mov.b64 %0, {%1, %2};" : "=l"(r) : "f"(x), "f"(y));
    return r;
}
__device__ __forceinline__ float2 unpk2(unsigned long long v) {
    float x, y;
    asm("mov.b64 {%0, %1}, %2;" : "=f"(x), "=f"(y) : "l"(v));
    return make_float2(x, y);
}
#define FMA2(d, a, b, c) \
    asm("fma.rn.f32x2 %0, %1, %2, %3;" : "=l"(d) : "l"(a), "l"(b), "l"(c))

// ---------------- scratch (static device globals; no allocation) ----------------
__device__ float  g_h[NN * HH];     // residual stream (fp32)
__device__ __half g_hhA[NN * HH];   // ping-pong message table m' = (relu(h2)+eps)*log2e
__device__ __half g_hhB[NN * HH];   //   (e^m = 2^m'; base h2 = ln2*m' - eps)
__device__ int    g_deg[NN];
__device__ int    g_cur[NN];
__device__ int    g_off[NN + 1];
__device__ int    g_srt_src[EE];    // src indices bucketed by dst

// ---------------- CSR build ----------------
__global__ void k_zero() {
    int i = blockIdx.x * blockDim.x + threadIdx.x;
    if (i < NN) { g_deg[i] = 0; g_cur[i] = 0; }
}

__global__ void k_hist(const int* __restrict__ dst) {
    int e = blockIdx.x * blockDim.x + threadIdx.x;
    if (e < EE) atomicAdd(&g_deg[dst[e]], 1);
}

__global__ void k_scan() {
    __shared__ int part[1024];
    const int tid = threadIdx.x;
    const int CH = (NN + 1023) / 1024;  // 49
    int beg = tid * CH;
    int end = min(beg + CH, NN);
    int s = 0;
    for (int i = beg; i < end; i++) s += g_deg[i];
    part[tid] = s;
    __syncthreads();
    for (int off = 1; off < 1024; off <<= 1) {
        int v = 0;
        if (tid >= off) v = part[tid - off];
        __syncthreads();
        if (tid >= off) part[tid] += v;
        __syncthreads();
    }
    int run = part[tid] - s;
    for (int i = beg; i < end; i++) { g_off[i] = run; run += g_deg[i]; }
    if (tid == 1023) g_off[NN] = run;
}

__global__ void k_scatter(const int* __restrict__ src,
                          const int* __restrict__ dst) {
    int e = blockIdx.x * blockDim.x + threadIdx.x;
    if (e < EE) {
        int d = dst[e];
        int pos = g_off[d] + atomicAdd(&g_cur[d], 1);
        g_srt_src[pos] = src[e];
    }
}

// ---------------- encoder: h = x @ enc_W + enc_b -> g_h, g_hhA(m') ----------------
__global__ void __launch_bounds__(256) k_enc(const float* __restrict__ x,
                                             const float* __restrict__ W,
                                             const float* __restrict__ b) {
    __shared__ float Ws[INF_ * HH];   // 32 KB
    __shared__ float xs[16][INF_];    // 8 KB
    int tid = threadIdx.x;
    int nl = tid >> 6, j = tid & 63;
    int n0 = blockIdx.x * 16;
    for (int i = tid; i < INF_ * HH; i += 256) Ws[i] = W[i];
    for (int i = tid; i < 16 * INF_; i += 256) {
        int node = i >> 7, f = i & 127;
        xs[node][f] = (n0 + node < NN) ? x[(n0 + node) * INF_ + f] : 0.f;
    }
    __syncthreads();
    float bj = b[j];
    float acc[4] = {bj, bj, bj, bj};
    #pragma unroll
    for (int k = 0; k < INF_; k++) {
        float w = Ws[k * HH + j];
        #pragma unroll
        for (int i = 0; i < 4; i++) acc[i] = fmaf(xs[nl + 4 * i][k], w, acc[i]);
    }
    #pragma unroll
    for (int i = 0; i < 4; i++) {
        int n = n0 + nl + 4 * i;
        if (n < NN) {
            g_h[n * HH + j] = acc[i];   // layer-0 fp32 base (pre-relu, may be negative)
            g_hhA[n * HH + j] = __float2half_rn((fmaxf(acc[i], 0.f) + MSG_EPS) * LOG2E);
        }
    }
}

// ---------------- fused warp-autonomous layer kernel (pair + FFMA2 GEMM) ----------------
// Each warp owns node pairs (2p, 2p+1) grid-stride; no cross-warp barriers after
// the one-time Ws load. Per pair:
//   agg: gather half2 m' table; e^m = h2exp2(m') (one f16x2 MUFU/edge-lane);
//        base = ln2*m'_self - eps (layers>=1) or fp32 base0 (layer 0)
//   stage t DUPLICATED ({t,t} u64) per node -> GEMM inner loop is
//        3 LDS.64 + 2 FFMA2 per k (vs 2 LDS + 8 FFMA scalar)
//   + bias + residual -> g_h; LayerNorm+ReLU -> hhdst (half m' table only)
__global__ void __launch_bounds__(256, 6) k_layer(const float* __restrict__ W,
                                                  const float* __restrict__ b,
                                                  const float* __restrict__ gma,
                                                  const float* __restrict__ bta,
                                                  const __half2* __restrict__ hhsrc,
                                                  __half2* __restrict__ hhdst,
                                                  const float* __restrict__ base0,
                                                  int use_f32base,
                                                  int res, int write_h2) {
    __shared__ float Ws[HH * HH];                      // 16 KB
    __shared__ unsigned long long tsx[8][HH];          // {t0,t0} per feature, 4 KB
    __shared__ unsigned long long tsy[8][HH];          // {t1,t1} per feature, 4 KB
    int tid = threadIdx.x;
    int wid = tid >> 5, lane = tid & 31;

    for (int i = tid; i < HH * HH; i += 256) Ws[i] = W[i];
    __syncthreads();                     // the only block barrier

    const unsigned long long* Wq = (const unsigned long long*)Ws;  // Wq[k*32+lane]
    float2 bv = ((const float2*)b)[lane];
    float2 gg = ((const float2*)gma)[lane];
    float2 bb = ((const float2*)bta)[lane];

    for (int p = blockIdx.x * 8 + wid; p < NP; p += PGRID * 8) {
        int n0 = 2 * p;
        // ---- aggregation for both nodes of the pair ----
        float2 o[2];
        #pragma unroll
        for (int t = 0; t < 2; t++) {
            int n = n0 + t;
            int beg = g_off[n], end = g_off[n + 1];
            float d0 = 0.f, d1 = 0.f, s0 = 0.f, s1 = 0.f;
            int e = beg;
            for (; e + 4 <= end; e += 4) {       // 4 independent gathers in flight
                int a0 = g_srt_src[e];
                int a1 = g_srt_src[e + 1];
                int a2 = g_srt_src[e + 2];
                int a3 = g_srt_src[e + 3];
                __half2 m0 = hhsrc[a0 * 32 + lane];   // m' values
                __half2 m1 = hhsrc[a1 * 32 + lane];
                __half2 m2 = hhsrc[a2 * 32 + lane];
                __half2 m3 = hhsrc[a3 * 32 + lane];
                float2 ef, mf;
                ef = __half22float2(h2exp2(m0)); mf = __half22float2(m0);
                d0 += ef.x; s0 = fmaf(mf.x, ef.x, s0);
                d1 += ef.y; s1 = fmaf(mf.y, ef.y, s1);
                ef = __half22float2(h2exp2(m1)); mf = __half22float2(m1);
                d0 += ef.x; s0 = fmaf(mf.x, ef.x, s0);
                d1 += ef.y; s1 = fmaf(mf.y, ef.y, s1);
                ef = __half22float2(h2exp2(m2)); mf = __half22float2(m2);
                d0 += ef.x; s0 = fmaf(mf.x, ef.x, s0);
                d1 += ef.y; s1 = fmaf(mf.y, ef.y, s1);
                ef = __half22float2(h2exp2(m3)); mf = __half22float2(m3);
                d0 += ef.x; s0 = fmaf(mf.x, ef.x, s0);
                d1 += ef.y; s1 = fmaf(mf.y, ef.y, s1);
            }
            for (; e < end; e++) {
                int s = g_srt_src[e];
                __half2 mh = hhsrc[s * 32 + lane];
                float2 ef = __half22float2(h2exp2(mh));
                float2 mf = __half22float2(mh);
                d0 += ef.x; s0 = fmaf(mf.x, ef.x, s0);
                d1 += ef.y; s1 = fmaf(mf.y, ef.y, s1);
            }
            float2 base2;
            if (use_f32base) {
                base2 = ((const float2*)(base0 + n * HH))[lane];   // layer 0: fp32 h
            } else {
                float2 ms = __half22float2(hhsrc[n * 32 + lane]);  // own m'
                base2.x = ms.x * LN2 - MSG_EPS;                    // h2 = ln2*m' - eps
                base2.y = ms.y * LN2 - MSG_EPS;
            }
            o[t].x = base2.x + (LN2 * s0) / fmaxf(d0, 1e-16f);   // empty segment -> +0
            o[t].y = base2.y + (LN2 * s1) / fmaxf(d1, 1e-16f);
        }
        // stage duplicated {t,t} per feature into per-warp smem
        tsx[wid][2 * lane]     = pk2(o[0].x, o[0].x);
        tsx[wid][2 * lane + 1] = pk2(o[0].y, o[0].y);
        tsy[wid][2 * lane]     = pk2(o[1].x, o[1].x);
        tsy[wid][2 * lane + 1] = pk2(o[1].y, o[1].y);
        __syncwarp();

        // ---- per-warp GEMM with FFMA2 + bias + residual ----
        float2 h0 = res ? ((const float2*)(g_h + n0 * HH))[lane] : make_float2(0.f, 0.f);
        float2 h1 = res ? ((const float2*)(g_h + (n0 + 1) * HH))[lane] : make_float2(0.f, 0.f);
        unsigned long long A0 = pk2(bv.x + h0.x, bv.y + h0.y);
        unsigned long long A1 = pk2(bv.x + h1.x, bv.y + h1.y);
        #pragma unroll
        for (int k = 0; k < HH; k++) {
            unsigned long long w2 = Wq[k * 32 + lane];   // W[k][2lane..2lane+1]
            unsigned long long tx = tsx[wid][k];         // {t0[k], t0[k]}
            unsigned long long ty = tsy[wid][k];         // {t1[k], t1[k]}
            FMA2(A0, tx, w2, A0);
            FMA2(A1, ty, w2, A1);
        }
        __syncwarp();                               // done reading ts before next iter
        float2 a0 = unpk2(A0);
        float2 a1 = unpk2(A1);
        ((float2*)(g_h + n0 * HH))[lane] = a0;
        ((float2*)(g_h + (n0 + 1) * HH))[lane] = a1;

        // ---- LayerNorm + ReLU from registers -> half m' table only ----
        if (write_h2) {
            #pragma unroll
            for (int t = 0; t < 2; t++) {
                float2 v = t ? a1 : a0;
                float s = v.x + v.y;
                #pragma unroll
                for (int off = 16; off; off >>= 1) s += __shfl_xor_sync(0xffffffffu, s, off);
                float mu = s * (1.f / 64.f);
                float dx = v.x - mu, dy = v.y - mu;
                float vs = dx * dx + dy * dy;
                #pragma unroll
                for (int off = 16; off; off >>= 1) vs += __shfl_xor_sync(0xffffffffu, vs, off);
                float rs = rsqrtf(vs * (1.f / 64.f) + LN_EPS);
                float2 o2;
                o2.x = fmaxf(fmaf(dx * rs, gg.x, bb.x), 0.f);
                o2.y = fmaxf(fmaf(dy * rs, gg.y, bb.y), 0.f);
                hhdst[(n0 + t) * 32 + lane] =
                    __floats2half2_rn((o2.x + MSG_EPS) * LOG2E, (o2.y + MSG_EPS) * LOG2E);
            }
        }
    }
}

// ---------------- predictor: out = h @ pred_W + pred_b (16 nodes/block, reg-blocked) ----------------
__global__ void __launch_bounds__(224) k_pred(const float* __restrict__ W,
                                              const float* __restrict__ b,
                                              float* __restrict__ out) {
    __shared__ float Ws[HH * OUTF];  // 28 KB
    __shared__ float hs[16][HH];     // 4 KB
    int tid = threadIdx.x;
    int nl = tid / OUTF, j = tid % OUTF;   // nl in 0..1
    int n0 = blockIdx.x * 16;
    for (int i = tid; i < HH * OUTF; i += 224) Ws[i] = W[i];
    for (int i = tid; i < 16 * HH; i += 224) {
        int node = i >> 6, f = i & 63;
        int n = n0 + node;
        hs[node][f] = (n < NN) ? g_h[n * HH + f] : 0.f;
    }
    __syncthreads();
    float bj = b[j];
    float acc[8];
    #pragma unroll
    for (int i = 0; i < 8; i++) acc[i] = bj;
    #pragma unroll
    for (int k = 0; k < HH; k++) {
        float w = Ws[k * OUTF + j];
        #pragma unroll
        for (int i = 0; i < 8; i++) acc[i] = fmaf(hs[nl + 2 * i][k], w, acc[i]);
    }
    #pragma unroll
    for (int i = 0; i < 8; i++) {
        int n = n0 + nl + 2 * i;
        if (n < NN) out[n * OUTF + j] = acc[i];
    }
}

// ---------------- launch ----------------
extern "C" void kernel_launch(void* const* d_in, const int* in_sizes, int n_in,
                              void* d_out, int out_size) {
    const float* x      = (const float*)d_in[0];
    const int*   ei     = (const int*)d_in[1];   // int32 (jax x64 disabled)
    const float* enc_W  = (const float*)d_in[2];
    const float* enc_b  = (const float*)d_in[3];
    const float* ln_g   = (const float*)d_in[4];
    const float* ln_b   = (const float*)d_in[5];
    const float* mlp_W  = (const float*)d_in[6];
    const float* mlp_b  = (const float*)d_in[7];
    const float* pred_W = (const float*)d_in[8];
    const float* pred_b = (const float*)d_in[9];
    float*       out    = (float*)d_out;

    const int* src = ei;
    const int* dst = ei + EE;

    // CSR build (counting sort by dst)
    k_zero<<<(NN + 255) / 256, 256>>>();
    k_hist<<<(EE + 255) / 256, 256>>>(dst);
    k_scan<<<1, 1024>>>();
    k_scatter<<<(EE + 255) / 256, 256>>>(src, dst);

    // encoder (g_h + half m' table hhA)
    k_enc<<<(NN + 15) / 16, 256>>>(x, enc_W, enc_b);

    float* hptr = nullptr;
    __half *hhA = nullptr, *hhB = nullptr;
    cudaGetSymbolAddress((void**)&hptr, g_h);
    cudaGetSymbolAddress((void**)&hhA, g_hhA);
    cudaGetSymbolAddress((void**)&hhB, g_hhB);

    // layer i: m'-table source = hh[i%2], output -> hh[(i+1)%2]
    for (int i = 0; i < LL; i++) {
        const __half2* hhsrc = (const __half2*)((i & 1) ? hhB : hhA);
        __half2*       hhdst = (__half2*)((i & 1) ? hhA : hhB);
        k_layer<<<PGRID, 256>>>(mlp_W + i * HH * HH, mlp_b + i * HH,
                                ln_g + i * HH, ln_b + i * HH,
                                hhsrc, hhdst,
                                /*base0=*/hptr, /*use_f32base=*/(i == 0) ? 1 : 0,
                                /*res=*/(i > 0) ? 1 : 0,
                                /*write_h2=*/(i < LL - 1) ? 1 : 0);
    }

    // predictor
    k_pred<<<(NN + 15) / 16, 224>>>(pred_W, pred_b, out);
}

// round 17
// speedup vs baseline: 1.0854x; 1.0854x over previous
#include <cuda_runtime.h>
#include <cuda_fp16.h>
#include <math.h>

#define NN 50000
#define EE 800000
#define HH 64
#define LL 14
#define INF_ 128
#define OUTF 112
#define MSG_EPS 1e-7f
#define LN_EPS 1e-5f
#define LOG2E 1.4426950408889634f
#define LN2   0.6931471805599453f

#define PGRID 912                 // 6 blocks/SM * 152 SMs
#define NP (NN / 2)               // node pairs: 25000

// ---------------- scratch (static device globals; no allocation) ----------------
__device__ float  g_h[NN * HH];     // residual stream (fp32)
__device__ __half g_hhA[NN * HH];   // ping-pong message table m' = (relu(h2)+eps)*log2e
__device__ __half g_hhB[NN * HH];   //   (e^m = 2^m'; base h2 = ln2*m' - eps)
__device__ int    g_deg[NN];
__device__ int    g_cur[NN];
__device__ int    g_off[NN + 1];
__device__ int    g_srt_src[EE];    // src indices bucketed by dst

// ---------------- CSR build ----------------
__global__ void k_zero() {
    int i = blockIdx.x * blockDim.x + threadIdx.x;
    if (i < NN) { g_deg[i] = 0; g_cur[i] = 0; }
}

__global__ void k_hist(const int* __restrict__ dst) {
    int e = blockIdx.x * blockDim.x + threadIdx.x;
    if (e < EE) atomicAdd(&g_deg[dst[e]], 1);
}

__global__ void k_scan() {
    __shared__ int part[1024];
    const int tid = threadIdx.x;
    const int CH = (NN + 1023) / 1024;  // 49
    int beg = tid * CH;
    int end = min(beg + CH, NN);
    int s = 0;
    for (int i = beg; i < end; i++) s += g_deg[i];
    part[tid] = s;
    __syncthreads();
    for (int off = 1; off < 1024; off <<= 1) {
        int v = 0;
        if (tid >= off) v = part[tid - off];
        __syncthreads();
        if (tid >= off) part[tid] += v;
        __syncthreads();
    }
    int run = part[tid] - s;
    for (int i = beg; i < end; i++) { g_off[i] = run; run += g_deg[i]; }
    if (tid == 1023) g_off[NN] = run;
}

__global__ void k_scatter(const int* __restrict__ src,
                          const int* __restrict__ dst) {
    int e = blockIdx.x * blockDim.x + threadIdx.x;
    if (e < EE) {
        int d = dst[e];
        int pos = g_off[d] + atomicAdd(&g_cur[d], 1);
        g_srt_src[pos] = src[e];
    }
}

// ---------------- encoder: h = x @ enc_W + enc_b -> g_h, g_hhA(m') ----------------
__global__ void __launch_bounds__(256) k_enc(const float* __restrict__ x,
                                             const float* __restrict__ W,
                                             const float* __restrict__ b) {
    __shared__ float Ws[INF_ * HH];   // 32 KB
    __shared__ float xs[16][INF_];    // 8 KB
    int tid = threadIdx.x;
    int nl = tid >> 6, j = tid & 63;
    int n0 = blockIdx.x * 16;
    for (int i = tid; i < INF_ * HH; i += 256) Ws[i] = W[i];
    for (int i = tid; i < 16 * INF_; i += 256) {
        int node = i >> 7, f = i & 127;
        xs[node][f] = (n0 + node < NN) ? x[(n0 + node) * INF_ + f] : 0.f;
    }
    __syncthreads();
    float bj = b[j];
    float acc[4] = {bj, bj, bj, bj};
    #pragma unroll
    for (int k = 0; k < INF_; k++) {
        float w = Ws[k * HH + j];
        #pragma unroll
        for (int i = 0; i < 4; i++) acc[i] = fmaf(xs[nl + 4 * i][k], w, acc[i]);
    }
    #pragma unroll
    for (int i = 0; i < 4; i++) {
        int n = n0 + nl + 4 * i;
        if (n < NN) {
            g_h[n * HH + j] = acc[i];   // layer-0 fp32 base (pre-relu, may be negative)
            g_hhA[n * HH + j] = __float2half_rn((fmaxf(acc[i], 0.f) + MSG_EPS) * LOG2E);
        }
    }
}

// accumulate one gathered half2 m' into (d0,d1,s0,s1)
#define AGG_STEP(mh) do {                         \
    float2 ef_ = __half22float2(h2exp2(mh));      \
    float2 mf_ = __half22float2(mh);              \
    d0 += ef_.x; s0 = fmaf(mf_.x, ef_.x, s0);     \
    d1 += ef_.y; s1 = fmaf(mf_.y, ef_.y, s1);     \
} while (0)

// ---------------- fused warp-autonomous layer kernel (pair, MLP-8) ----------------
// Each warp owns node pairs (2p, 2p+1) grid-stride; no cross-warp barriers after
// the one-time Ws load. Latency structure:
//   - residual g_h reads + self-base m' loads hoisted ABOVE the edge loops
//   - edge loop unrolled 8-wide (8 independent gathers in flight)
// Then per-warp 64x64 GEMM + bias + residual -> g_h; LN+ReLU -> hhdst.
__global__ void __launch_bounds__(256, 6) k_layer(const float* __restrict__ W,
                                                  const float* __restrict__ b,
                                                  const float* __restrict__ gma,
                                                  const float* __restrict__ bta,
                                                  const __half2* __restrict__ hhsrc,
                                                  __half2* __restrict__ hhdst,
                                                  const float* __restrict__ base0,
                                                  int use_f32base,
                                                  int res, int write_h2) {
    __shared__ float  Ws[HH * HH];       // 16 KB, block-shared (read-only after load)
    __shared__ float2 tst[8][HH];        // per-warp stage: (t0[k], t1[k]) pairs, 4 KB
    int tid = threadIdx.x;
    int wid = tid >> 5, lane = tid & 31;

    for (int i = tid; i < HH * HH; i += 256) Ws[i] = W[i];
    __syncthreads();                     // the only block barrier

    const float2* Wv = (const float2*)Ws;  // Wv[k*32 + lane] = W[k][2lane..2lane+1]
    float2 bv = ((const float2*)b)[lane];
    float2 gg = ((const float2*)gma)[lane];
    float2 bb = ((const float2*)bta)[lane];

    for (int p = blockIdx.x * 8 + wid; p < NP; p += PGRID * 8) {
        int n0 = 2 * p;

        // ---- hoisted pair-independent loads (hidden under the edge loops) ----
        float2 h0 = res ? ((const float2*)(g_h + n0 * HH))[lane] : make_float2(0.f, 0.f);
        float2 h1 = res ? ((const float2*)(g_h + (n0 + 1) * HH))[lane] : make_float2(0.f, 0.f);
        float2 base[2];
        if (use_f32base) {
            base[0] = ((const float2*)(base0 + n0 * HH))[lane];
            base[1] = ((const float2*)(base0 + (n0 + 1) * HH))[lane];
        } else {
            float2 ms0 = __half22float2(hhsrc[n0 * 32 + lane]);        // own m'
            float2 ms1 = __half22float2(hhsrc[(n0 + 1) * 32 + lane]);
            base[0] = make_float2(ms0.x * LN2 - MSG_EPS, ms0.y * LN2 - MSG_EPS);
            base[1] = make_float2(ms1.x * LN2 - MSG_EPS, ms1.y * LN2 - MSG_EPS);
        }
        int beg0 = g_off[n0], end0 = g_off[n0 + 1], end1 = g_off[n0 + 2];

        // ---- aggregation for both nodes of the pair (8 gathers in flight) ----
        float2 o[2];
        #pragma unroll
        for (int t = 0; t < 2; t++) {
            int beg = t ? end0 : beg0;
            int end = t ? end1 : end0;
            float d0 = 0.f, d1 = 0.f, s0 = 0.f, s1 = 0.f;
            int e = beg;
            for (; e + 8 <= end; e += 8) {       // 8 independent gathers in flight
                int a0 = g_srt_src[e];
                int a1 = g_srt_src[e + 1];
                int a2 = g_srt_src[e + 2];
                int a3 = g_srt_src[e + 3];
                int a4 = g_srt_src[e + 4];
                int a5 = g_srt_src[e + 5];
                int a6 = g_srt_src[e + 6];
                int a7 = g_srt_src[e + 7];
                __half2 m0 = hhsrc[a0 * 32 + lane];
                __half2 m1 = hhsrc[a1 * 32 + lane];
                __half2 m2 = hhsrc[a2 * 32 + lane];
                __half2 m3 = hhsrc[a3 * 32 + lane];
                __half2 m4 = hhsrc[a4 * 32 + lane];
                __half2 m5 = hhsrc[a5 * 32 + lane];
                __half2 m6 = hhsrc[a6 * 32 + lane];
                __half2 m7 = hhsrc[a7 * 32 + lane];
                AGG_STEP(m0); AGG_STEP(m1); AGG_STEP(m2); AGG_STEP(m3);
                AGG_STEP(m4); AGG_STEP(m5); AGG_STEP(m6); AGG_STEP(m7);
            }
            if (e + 4 <= end) {
                int a0 = g_srt_src[e];
                int a1 = g_srt_src[e + 1];
                int a2 = g_srt_src[e + 2];
                int a3 = g_srt_src[e + 3];
                __half2 m0 = hhsrc[a0 * 32 + lane];
                __half2 m1 = hhsrc[a1 * 32 + lane];
                __half2 m2 = hhsrc[a2 * 32 + lane];
                __half2 m3 = hhsrc[a3 * 32 + lane];
                AGG_STEP(m0); AGG_STEP(m1); AGG_STEP(m2); AGG_STEP(m3);
                e += 4;
            }
            for (; e < end; e++) {
                __half2 mh = hhsrc[g_srt_src[e] * 32 + lane];
                AGG_STEP(mh);
            }
            o[t].x = base[t].x + (LN2 * s0) / fmaxf(d0, 1e-16f);   // empty segment -> +0
            o[t].y = base[t].y + (LN2 * s1) / fmaxf(d1, 1e-16f);
        }
        // stage (t0[k], t1[k]) into per-warp smem
        tst[wid][2 * lane].x     = o[0].x;
        tst[wid][2 * lane + 1].x = o[0].y;
        tst[wid][2 * lane].y     = o[1].x;
        tst[wid][2 * lane + 1].y = o[1].y;
        __syncwarp();

        // ---- per-warp GEMM + bias + residual ----
        float2 a0 = make_float2(bv.x + h0.x, bv.y + h0.y);
        float2 a1 = make_float2(bv.x + h1.x, bv.y + h1.y);
        #pragma unroll
        for (int k = 0; k < HH; k++) {
            float2 w2 = Wv[k * 32 + lane];          // W[k][2lane], W[k][2lane+1]
            float2 tk = tst[wid][k];                // broadcast (t0[k], t1[k])
            a0.x = fmaf(tk.x, w2.x, a0.x);
            a0.y = fmaf(tk.x, w2.y, a0.y);
            a1.x = fmaf(tk.y, w2.x, a1.x);
            a1.y = fmaf(tk.y, w2.y, a1.y);
        }
        __syncwarp();                               // done reading tst before next iter
        ((float2*)(g_h + n0 * HH))[lane] = a0;
        ((float2*)(g_h + (n0 + 1) * HH))[lane] = a1;

        // ---- LayerNorm + ReLU from registers -> half m' table only ----
        if (write_h2) {
            #pragma unroll
            for (int t = 0; t < 2; t++) {
                float2 v = t ? a1 : a0;
                float s = v.x + v.y;
                #pragma unroll
                for (int off = 16; off; off >>= 1) s += __shfl_xor_sync(0xffffffffu, s, off);
                float mu = s * (1.f / 64.f);
                float dx = v.x - mu, dy = v.y - mu;
                float vs = dx * dx + dy * dy;
                #pragma unroll
                for (int off = 16; off; off >>= 1) vs += __shfl_xor_sync(0xffffffffu, vs, off);
                float rs = rsqrtf(vs * (1.f / 64.f) + LN_EPS);
                float2 o2;
                o2.x = fmaxf(fmaf(dx * rs, gg.x, bb.x), 0.f);
                o2.y = fmaxf(fmaf(dy * rs, gg.y, bb.y), 0.f);
                hhdst[(n0 + t) * 32 + lane] =
                    __floats2half2_rn((o2.x + MSG_EPS) * LOG2E, (o2.y + MSG_EPS) * LOG2E);
            }
        }
    }
}

// ---------------- predictor: out = h @ pred_W + pred_b (16 nodes/block, reg-blocked) ----------------
__global__ void __launch_bounds__(224) k_pred(const float* __restrict__ W,
                                              const float* __restrict__ b,
                                              float* __restrict__ out) {
    __shared__ float Ws[HH * OUTF];  // 28 KB
    __shared__ float hs[16][HH];     // 4 KB
    int tid = threadIdx.x;
    int nl = tid / OUTF, j = tid % OUTF;   // nl in 0..1
    int n0 = blockIdx.x * 16;
    for (int i = tid; i < HH * OUTF; i += 224) Ws[i] = W[i];
    for (int i = tid; i < 16 * HH; i += 224) {
        int node = i >> 6, f = i & 63;
        int n = n0 + node;
        hs[node][f] = (n < NN) ? g_h[n * HH + f] : 0.f;
    }
    __syncthreads();
    float bj = b[j];
    float acc[8];
    #pragma unroll
    for (int i = 0; i < 8; i++) acc[i] = bj;
    #pragma unroll
    for (int k = 0; k < HH; k++) {
        float w = Ws[k * OUTF + j];
        #pragma unroll
        for (int i = 0; i < 8; i++) acc[i] = fmaf(hs[nl + 2 * i][k], w, acc[i]);
    }
    #pragma unroll
    for (int i = 0; i < 8; i++) {
        int n = n0 + nl + 2 * i;
        if (n < NN) out[n * OUTF + j] = acc[i];
    }
}

// ---------------- launch ----------------
extern "C" void kernel_launch(void* const* d_in, const int* in_sizes, int n_in,
                              void* d_out, int out_size) {
    const float* x      = (const float*)d_in[0];
    const int*   ei     = (const int*)d_in[1];   // int32 (jax x64 disabled)
    const float* enc_W  = (const float*)d_in[2];
    const float* enc_b  = (const float*)d_in[3];
    const float* ln_g   = (const float*)d_in[4];
    const float* ln_b   = (const float*)d_in[5];
    const float* mlp_W  = (const float*)d_in[6];
    const float* mlp_b  = (const float*)d_in[7];
    const float* pred_W = (const float*)d_in[8];
    const float* pred_b = (const float*)d_in[9];
    float*       out    = (float*)d_out;

    const int* src = ei;
    const int* dst = ei + EE;

    // CSR build (counting sort by dst)
    k_zero<<<(NN + 255) / 256, 256>>>();
    k_hist<<<(EE + 255) / 256, 256>>>(dst);
    k_scan<<<1, 1024>>>();
    k_scatter<<<(EE + 255) / 256, 256>>>(src, dst);

    // encoder (g_h + half m' table hhA)
    k_enc<<<(NN + 15) / 16, 256>>>(x, enc_W, enc_b);

    float* hptr = nullptr;
    __half *hhA = nullptr, *hhB = nullptr;
    cudaGetSymbolAddress((void**)&hptr, g_h);
    cudaGetSymbolAddress((void**)&hhA, g_hhA);
    cudaGetSymbolAddress((void**)&hhB, g_hhB);

    // layer i: m'-table source = hh[i%2], output -> hh[(i+1)%2]
    for (int i = 0; i < LL; i++) {
        const __half2* hhsrc = (const __half2*)((i & 1) ? hhB : hhA);
        __half2*       hhdst = (__half2*)((i & 1) ? hhA : hhB);
        k_layer<<<PGRID, 256>>>(mlp_W + i * HH * HH, mlp_b + i * HH,
                                ln_g + i * HH, ln_b + i * HH,
                                hhsrc, hhdst,
                                /*base0=*/hptr, /*use_f32base=*/(i == 0) ? 1 : 0,
                                /*res=*/(i > 0) ? 1 : 0,
                                /*write_h2=*/(i < LL - 1) ? 1 : 0);
    }

    // predictor
    k_pred<<<(NN + 15) / 16, 224>>>(pred_W, pred_b, out);
}